// round 15
// baseline (speedup 1.0000x reference)
#include <cuda_runtime.h>
#include <cuda_fp16.h>
#include <math.h>
#include <cstdint>

#define N_NODES 50000
#define N_EDGES 800000

// ================= scratch =================
__device__ int   g_is64;
__device__ int   g_edeg[N_NODES];
__device__ float g_dinv[N_NODES];
__device__ int   g_rowptr[N_NODES + 1];
__device__ int   g_cursor[N_NODES];
__device__ int   g_col[N_EDGES];
__device__ float g_wedge[N_EDGES];

// fp16 buffers
__device__ __half g_h1[N_NODES * 128];
__device__ __half g_h2[N_NODES * 128];
__device__ __half g_xh[N_NODES * 128];
__device__ __half g_bufA[N_NODES * 256];
__device__ __half g_aggx[N_NODES * 128];
__device__ __half g_agg2[N_NODES * 256];
__device__ __half g_comb[N_NODES * 256];
__device__ __half g_wth[6][16384];
__device__ __half g_wtl[6][16384];

// ================= helpers =================
__device__ __forceinline__ uint32_t smem_u32(const void* p) {
    uint32_t a;
    asm("{ .reg .u64 t; cvta.to.shared.u64 t, %1; cvt.u32.u64 %0, t; }" : "=r"(a) : "l"(p));
    return a;
}
__device__ __forceinline__ void ldsm_x4(uint32_t* r, uint32_t addr) {
    asm volatile("ldmatrix.sync.aligned.m8n8.x4.shared.b16 {%0,%1,%2,%3}, [%4];"
                 : "=r"(r[0]), "=r"(r[1]), "=r"(r[2]), "=r"(r[3]) : "r"(addr));
}
__device__ __forceinline__ void ldsm_x2(uint32_t* r, uint32_t addr) {
    asm volatile("ldmatrix.sync.aligned.m8n8.x2.shared.b16 {%0,%1}, [%2];"
                 : "=r"(r[0]), "=r"(r[1]) : "r"(addr));
}
__device__ __forceinline__ void mma_f16(float* d, const uint32_t* a, const uint32_t* b) {
    asm volatile("mma.sync.aligned.m16n8k16.row.col.f32.f16.f16.f32 "
                 "{%0,%1,%2,%3}, {%4,%5,%6,%7}, {%8,%9}, {%0,%1,%2,%3};"
                 : "+f"(d[0]), "+f"(d[1]), "+f"(d[2]), "+f"(d[3])
                 : "r"(a[0]), "r"(a[1]), "r"(a[2]), "r"(a[3]), "r"(b[0]), "r"(b[1]));
}
__device__ __forceinline__ void split_f16(float v, __half& h, __half& l) {
    __half hb = __float2half_rn(v);
    h = hb;
    l = __float2half_rn(v - __half2float(hb));
}

// ================= fused: detect + edeg zero + weight prep =================
struct PrepB { const float* W[6]; int K[6]; int N[6]; };
__global__ void k_detect_init_prep(const int* __restrict__ ei32, PrepB p, int nInitBlocks) {
    if ((int)blockIdx.x < nInitBlocks) {
        int i = blockIdx.x * blockDim.x + threadIdx.x;
        if (i < N_NODES) g_edeg[i] = 0;
        if (blockIdx.x == 0) {
            __shared__ int nz;
            if (threadIdx.x == 0) nz = 0;
            __syncthreads();
            int local = 0;
            for (int q = threadIdx.x; q < 2048; q += blockDim.x)
                if (ei32[2 * q + 1] != 0) local = 1;
            if (local) atomicOr(&nz, 1);
            __syncthreads();
            if (threadIdx.x == 0) g_is64 = nz ? 0 : 1;
        }
    } else {
        int b = blockIdx.x - nInitBlocks;   // 0..5
        const float* W = p.W[b];
        int K = p.K[b], N = p.N[b];
        for (int idx = threadIdx.x; idx < K * N; idx += blockDim.x) {
            int k = idx / N, n = idx % N;
            split_f16(W[idx], g_wth[b][n * K + k], g_wtl[b][n * K + k]);
        }
    }
}

// ================= fused: count + x->fp16 =================
__global__ void k_count_convx(const int* __restrict__ ei32, const float* __restrict__ x,
                              __half* __restrict__ xh, int nCountBlocks) {
    if ((int)blockIdx.x < nCountBlocks) {
        int e = blockIdx.x * blockDim.x + threadIdx.x;
        if (e < N_EDGES) {
            int d = g_is64 ? ei32[2 * (N_EDGES + e)] : ei32[N_EDGES + e];
            atomicAdd(&g_edeg[d], 1);
        }
    } else {
        int i = (blockIdx.x - nCountBlocks) * blockDim.x + threadIdx.x;
        const float4* xp = reinterpret_cast<const float4*>(x) + 2 * (size_t)i;
        float4 a = xp[0], b = xp[1];
        __half2 h[4];
        h[0] = {__float2half_rn(a.x), __float2half_rn(a.y)};
        h[1] = {__float2half_rn(a.z), __float2half_rn(a.w)};
        h[2] = {__float2half_rn(b.x), __float2half_rn(b.y)};
        h[3] = {__float2half_rn(b.z), __float2half_rn(b.w)};
        reinterpret_cast<uint4*>(xh)[i] = *reinterpret_cast<uint4*>(h);
    }
}

__global__ void k_scan_dinv() {
    __shared__ int part[1024];
    const int t = threadIdx.x;
    const int CH = (N_NODES + 1023) / 1024;
    int start = t * CH;
    int s = 0;
    for (int i = 0; i < CH; i++) { int idx = start + i; if (idx < N_NODES) s += g_edeg[idx]; }
    part[t] = s;
    __syncthreads();
    for (int off = 1; off < 1024; off <<= 1) {
        int v = (t >= off) ? part[t - off] : 0;
        __syncthreads();
        part[t] += v;
        __syncthreads();
    }
    int run = (t == 0) ? 0 : part[t - 1];
    for (int i = 0; i < CH; i++) {
        int idx = start + i;
        if (idx < N_NODES) {
            g_rowptr[idx] = run;
            g_cursor[idx] = run;
            g_dinv[idx] = rsqrtf((float)(g_edeg[idx] + 1));
            run += g_edeg[idx];
        }
    }
    if (t == 1023) g_rowptr[N_NODES] = run;
}

__global__ void k_fill(const int* __restrict__ ei32) {
    int e = blockIdx.x * blockDim.x + threadIdx.x;
    if (e < N_EDGES) {
        int s, d;
        if (g_is64) { s = ei32[2 * e]; d = ei32[2 * (N_EDGES + e)]; }
        else        { s = ei32[e];     d = ei32[N_EDGES + e]; }
        int p = atomicAdd(&g_cursor[d], 1);
        g_col[p] = s;
        g_wedge[p] = g_dinv[s] * g_dinv[d];
    }
}

// ================= warp-per-node aggregation (fp16 gather) =================
__global__ __launch_bounds__(256, 8) void k_agg128(const __half* __restrict__ in,
                                                   __half* __restrict__ oh) {
    const int warp = threadIdx.x >> 5, lane = threadIdx.x & 31;
    const int n = blockIdx.x * 8 + warp;
    const int c4 = lane * 4;
    float dn = g_dinv[n];
    float acc0, acc1, acc2, acc3;
    {
        uint2 sv = *reinterpret_cast<const uint2*>(in + (size_t)n * 128 + c4);
        __half2 s0 = *reinterpret_cast<__half2*>(&sv.x);
        __half2 s1 = *reinterpret_cast<__half2*>(&sv.y);
        float w = dn * dn;
        acc0 = w * __half2float(s0.x); acc1 = w * __half2float(s0.y);
        acc2 = w * __half2float(s1.x); acc3 = w * __half2float(s1.y);
    }
    const int beg = g_rowptr[n], end = g_rowptr[n + 1];
    for (int base = beg; base < end; base += 32) {
        int cnt = end - base; if (cnt > 32) cnt = 32;
        int   col = 0; float wt = 0.0f;
        if (lane < cnt) { col = g_col[base + lane]; wt = g_wedge[base + lane]; }
        for (int j = 0; j < cnt; j++) {
            int   idx = __shfl_sync(0xFFFFFFFFu, col, j);
            float ww  = __shfl_sync(0xFFFFFFFFu, wt,  j);
            uint2 gv = *reinterpret_cast<const uint2*>(in + (size_t)idx * 128 + c4);
            __half2 g0 = *reinterpret_cast<__half2*>(&gv.x);
            __half2 g1 = *reinterpret_cast<__half2*>(&gv.y);
            acc0 += ww * __half2float(g0.x); acc1 += ww * __half2float(g0.y);
            acc2 += ww * __half2float(g1.x); acc3 += ww * __half2float(g1.y);
        }
    }
    __half2 o0 = {__float2half_rn(acc0), __float2half_rn(acc1)};
    __half2 o1 = {__float2half_rn(acc2), __float2half_rn(acc3)};
    *reinterpret_cast<uint2*>(oh + (size_t)n * 128 + c4) = make_uint2(
        *reinterpret_cast<uint32_t*>(&o0), *reinterpret_cast<uint32_t*>(&o1));
}

__global__ __launch_bounds__(256, 8) void k_agg256(const __half* __restrict__ in,
                                                   __half* __restrict__ oh) {
    const int warp = threadIdx.x >> 5, lane = threadIdx.x & 31;
    const int n = blockIdx.x * 8 + warp;
    const int c8 = lane * 8;
    float dn = g_dinv[n];
    float acc[8];
    {
        uint4 sv = *reinterpret_cast<const uint4*>(in + (size_t)n * 256 + c8);
        const __half2* sh = reinterpret_cast<const __half2*>(&sv);
        float w = dn * dn;
#pragma unroll
        for (int q = 0; q < 4; q++) {
            acc[2 * q]     = w * __half2float(sh[q].x);
            acc[2 * q + 1] = w * __half2float(sh[q].y);
        }
    }
    const int beg = g_rowptr[n], end = g_rowptr[n + 1];
    for (int base = beg; base < end; base += 32) {
        int cnt = end - base; if (cnt > 32) cnt = 32;
        int   col = 0; float wt = 0.0f;
        if (lane < cnt) { col = g_col[base + lane]; wt = g_wedge[base + lane]; }
        for (int j = 0; j < cnt; j++) {
            int   idx = __shfl_sync(0xFFFFFFFFu, col, j);
            float ww  = __shfl_sync(0xFFFFFFFFu, wt,  j);
            uint4 gv = *reinterpret_cast<const uint4*>(in + (size_t)idx * 256 + c8);
            const __half2* gh = reinterpret_cast<const __half2*>(&gv);
#pragma unroll
            for (int q = 0; q < 4; q++) {
                acc[2 * q]     += ww * __half2float(gh[q].x);
                acc[2 * q + 1] += ww * __half2float(gh[q].y);
            }
        }
    }
    __half2 hv[4];
#pragma unroll
    for (int q = 0; q < 4; q++)
        hv[q] = {__float2half_rn(acc[2 * q]), __float2half_rn(acc[2 * q + 1])};
    *reinterpret_cast<uint4*>(oh + (size_t)n * 256 + c8) = *reinterpret_cast<uint4*>(hv);
}

// ================= fp16 2-pass mma.sync GEMM =================
struct MJobs {
    const __half* A[3];
    const __half* Bh[3];
    const __half* Bl[3];
    const float*  bias[3];
    float*        C[3];
    __half*       Ch[3];
    int           lda[3];
    int           ldc[3];
    int           split[3];
};

// Shared mainloop body: assumes A in smem[0..AB), B split in smem[AB..AB+2*BB).
template <int THREADS, int BM, int NN, int KK, int MI, int NI>
__device__ __forceinline__ void mma_body(
    uint32_t sbase, const uint32_t* abyte, const int* rx,
    const uint32_t* bbyte, const int* nx, int kaddA, int kaddB,
    float acc[][8][4])    // generous bounds; MI<=4, NI<=4
{
    constexpr int AB  = BM * KK * 2;
    constexpr int BB  = NN * KK * 2;
    constexpr int KSTEPS = KK / 16;
#pragma unroll 1
    for (int pass = 0; pass < 2; pass++) {
        const uint32_t aoff = sbase;
        const uint32_t boff = sbase + AB + pass * BB;
#pragma unroll
        for (int s = 0; s < KSTEPS; s++) {
            const int kc = s * 2;
            uint32_t bf[NI][2];
#pragma unroll
            for (int ni = 0; ni < NI; ni++)
                ldsm_x2(bf[ni], boff + bbyte[ni] + ((uint32_t)((kc + kaddB) ^ nx[ni]) << 4));
#pragma unroll
            for (int mi = 0; mi < MI; mi++) {
                uint32_t af[4];
                ldsm_x4(af, aoff + abyte[mi] + ((uint32_t)((kc + kaddA) ^ rx[mi]) << 4));
#pragma unroll
                for (int ni = 0; ni < NI; ni++)
                    mma_f16(acc[mi][ni], af, bf[ni]);
            }
        }
    }
}

// Multi-job kernel: A loaded ONCE; loops over njobs weight sets (layer-1 shared-A).
template <int THREADS, int BM, int NN, int KK>
__global__ __launch_bounds__(THREADS, 2) void k_mma_shared(MJobs jobs, int njobs, int do_relu) {
    extern __shared__ __align__(16) unsigned char smem[];
    constexpr int NCH = KK / 8;
    constexpr int AB  = BM * KK * 2;
    constexpr int BB  = NN * KK * 2;
    constexpr int MWARPS = (THREADS == 512) ? 4 : 2;
    constexpr int MI  = BM / MWARPS / 16;
    constexpr int NI  = NN / 4 / 8;

    const int bm  = blockIdx.y * BM;
    const int tid = threadIdx.x;
    const int lane = tid & 31, warp = tid >> 5;
    const int wm = (warp >> 2) * (BM / MWARPS);
    const int wn = (warp & 3) * (NN / 4);

    // A load once
    {
        const __half* A = jobs.A[0];
        const int ldach = jobs.lda[0] / 8;
        uint4* s = reinterpret_cast<uint4*>(smem);
        for (int idx = tid; idx < BM * NCH; idx += THREADS) {
            int r = idx / NCH, cc = idx % NCH;
            long gr = bm + r; if (gr >= N_NODES) gr = N_NODES - 1;
            int sp = r * NCH + (cc ^ (r & 7));
            s[sp] = reinterpret_cast<const uint4*>(A)[gr * ldach + cc];
        }
    }

    const uint32_t sbase = smem_u32(smem);
    const int group = lane >> 3, within = lane & 7;
    const int kaddA = group >> 1;
    uint32_t abyte[MI]; int rx[MI];
    {
        int mrow = wm + (group & 1) * 8 + within;
#pragma unroll
        for (int mi = 0; mi < MI; mi++) {
            int r = mrow + mi * 16;
            abyte[mi] = (uint32_t)(r * NCH) << 4;
            rx[mi] = r & 7;
        }
    }
    const int laneB = lane & 15;
    const int kaddB = laneB >> 3, withinB = laneB & 7;
    uint32_t bbyte[NI]; int nx[NI];
#pragma unroll
    for (int ni = 0; ni < NI; ni++) {
        int r = wn + ni * 8 + withinB;
        bbyte[ni] = (uint32_t)(r * NCH) << 4;
        nx[ni] = r & 7;
    }
    const int g = lane >> 2, tc = lane & 3;

    for (int job = 0; job < njobs; job++) {
        __syncthreads();   // prev B consumed / A ready
        {
            const uint4* bh = reinterpret_cast<const uint4*>(jobs.Bh[job]);
            const uint4* bl = reinterpret_cast<const uint4*>(jobs.Bl[job]);
            uint4* sb = reinterpret_cast<uint4*>(smem + AB);
            for (int idx = tid; idx < NN * NCH; idx += THREADS) {
                int r = idx / NCH, cc = idx % NCH;
                int sp = r * NCH + (cc ^ (r & 7));
                sb[sp]           = bh[idx];
                sb[sp + BB / 16] = bl[idx];
            }
        }
        __syncthreads();

        float acc[MI][8][4];
#pragma unroll
        for (int mi = 0; mi < MI; mi++)
#pragma unroll
            for (int ni = 0; ni < NI; ni++)
#pragma unroll
                for (int q = 0; q < 4; q++) acc[mi][ni][q] = 0.0f;

        mma_body<THREADS, BM, NN, KK, MI, NI>(sbase, abyte, rx, bbyte, nx, kaddA, kaddB, acc);

        const float* bias = jobs.bias[job];
        __half* Ch = jobs.Ch[job];
        const int ldc = jobs.ldc[job];
#pragma unroll
        for (int mi = 0; mi < MI; mi++) {
#pragma unroll
            for (int ni = 0; ni < NI; ni++) {
                int n0 = wn + ni * 8 + tc * 2;
                float b0 = bias[n0], b1 = bias[n0 + 1];
                int m0 = bm + wm + mi * 16 + g;
                float v0 = acc[mi][ni][0] + b0, v1 = acc[mi][ni][1] + b1;
                float v2 = acc[mi][ni][2] + b0, v3 = acc[mi][ni][3] + b1;
                if (do_relu) {
                    v0 = fmaxf(v0, 0.0f); v1 = fmaxf(v1, 0.0f);
                    v2 = fmaxf(v2, 0.0f); v3 = fmaxf(v3, 0.0f);
                }
                if (m0 < N_NODES)
                    *reinterpret_cast<__half2*>(Ch + (size_t)m0 * ldc + n0) =
                        __half2{__float2half_rn(v0), __float2half_rn(v1)};
                if (m0 + 8 < N_NODES)
                    *reinterpret_cast<__half2*>(Ch + (size_t)(m0 + 8) * ldc + n0) =
                        __half2{__float2half_rn(v2), __float2half_rn(v3)};
            }
        }
    }
}

// Per-job kernel (grid.z = job): layer-2 (different A slices) and FC.
template <int THREADS, int BM, int NN, int KK>
__global__ __launch_bounds__(THREADS, 2) void k_mma(MJobs jobs, int do_relu) {
    extern __shared__ __align__(16) unsigned char smem[];
    constexpr int NCH = KK / 8;
    constexpr int AB  = BM * KK * 2;
    constexpr int BB  = NN * KK * 2;
    constexpr int MWARPS = (THREADS == 512) ? 4 : 2;
    constexpr int MI  = BM / MWARPS / 16;
    constexpr int NI  = NN / 4 / 8;

    const int job = blockIdx.z;
    const int bm  = blockIdx.y * BM;
    const int tid = threadIdx.x;
    const int lane = tid & 31, warp = tid >> 5;
    const int wm = (warp >> 2) * (BM / MWARPS);
    const int wn = (warp & 3) * (NN / 4);

    {
        const __half* A = jobs.A[job];
        const int ldach = jobs.lda[job] / 8;
        uint4* s = reinterpret_cast<uint4*>(smem);
        for (int idx = tid; idx < BM * NCH; idx += THREADS) {
            int r = idx / NCH, cc = idx % NCH;
            long gr = bm + r; if (gr >= N_NODES) gr = N_NODES - 1;
            int sp = r * NCH + (cc ^ (r & 7));
            s[sp] = reinterpret_cast<const uint4*>(A)[gr * ldach + cc];
        }
        const uint4* bh = reinterpret_cast<const uint4*>(jobs.Bh[job]);
        const uint4* bl = reinterpret_cast<const uint4*>(jobs.Bl[job]);
        uint4* sb = reinterpret_cast<uint4*>(smem + AB);
        for (int idx = tid; idx < NN * NCH; idx += THREADS) {
            int r = idx / NCH, cc = idx % NCH;
            int sp = r * NCH + (cc ^ (r & 7));
            sb[sp]           = bh[idx];
            sb[sp + BB / 16] = bl[idx];
        }
    }
    __syncthreads();

    const uint32_t sbase = smem_u32(smem);
    const int group = lane >> 3, within = lane & 7;
    const int kaddA = group >> 1;
    uint32_t abyte[MI]; int rx[MI];
    {
        int mrow = wm + (group & 1) * 8 + within;
#pragma unroll
        for (int mi = 0; mi < MI; mi++) {
            int r = mrow + mi * 16;
            abyte[mi] = (uint32_t)(r * NCH) << 4;
            rx[mi] = r & 7;
        }
    }
    const int laneB = lane & 15;
    const int kaddB = laneB >> 3, withinB = laneB & 7;
    uint32_t bbyte[NI]; int nx[NI];
#pragma unroll
    for (int ni = 0; ni < NI; ni++) {
        int r = wn + ni * 8 + withinB;
        bbyte[ni] = (uint32_t)(r * NCH) << 4;
        nx[ni] = r & 7;
    }

    float acc[MI][8][4];
#pragma unroll
    for (int mi = 0; mi < MI; mi++)
#pragma unroll
        for (int ni = 0; ni < NI; ni++)
#pragma unroll
            for (int q = 0; q < 4; q++) acc[mi][ni][q] = 0.0f;

    mma_body<THREADS, BM, NN, KK, MI, NI>(sbase, abyte, rx, bbyte, nx, kaddA, kaddB, acc);

    const float* bias = jobs.bias[job];
    float* C = jobs.C[job];
    __half* Ch = jobs.Ch[job];
    const int ldc = jobs.ldc[job];
    const int splt = jobs.split[job];
    const int g = lane >> 2, tc = lane & 3;
#pragma unroll
    for (int mi = 0; mi < MI; mi++) {
#pragma unroll
        for (int ni = 0; ni < NI; ni++) {
            int n0 = wn + ni * 8 + tc * 2;
            float b0 = bias[n0], b1 = bias[n0 + 1];
            int m0 = bm + wm + mi * 16 + g;
            float v0 = acc[mi][ni][0] + b0, v1 = acc[mi][ni][1] + b1;
            float v2 = acc[mi][ni][2] + b0, v3 = acc[mi][ni][3] + b1;
            if (do_relu) {
                v0 = fmaxf(v0, 0.0f); v1 = fmaxf(v1, 0.0f);
                v2 = fmaxf(v2, 0.0f); v3 = fmaxf(v3, 0.0f);
            }
            if (splt) {
                if (m0 < N_NODES)
                    *reinterpret_cast<__half2*>(Ch + (size_t)m0 * ldc + n0) =
                        __half2{__float2half_rn(v0), __float2half_rn(v1)};
                if (m0 + 8 < N_NODES)
                    *reinterpret_cast<__half2*>(Ch + (size_t)(m0 + 8) * ldc + n0) =
                        __half2{__float2half_rn(v2), __float2half_rn(v3)};
            } else {
                if (m0 < N_NODES)
                    *reinterpret_cast<float2*>(C + (size_t)m0 * ldc + n0) = make_float2(v0, v1);
                if (m0 + 8 < N_NODES)
                    *reinterpret_cast<float2*>(C + (size_t)(m0 + 8) * ldc + n0) = make_float2(v2, v3);
            }
        }
    }
}

// ================= attention fusion (fp16 h1/h2) =================
__global__ void k_attn(const float* __restrict__ watt, const float* __restrict__ batt) {
    const int half = threadIdx.x >> 7;
    const int c = threadIdx.x & 127;
    const int n = blockIdx.x * 2 + half;
    float h1v = __half2float(g_h1[n * 128 + c]);
    float h2v = __half2float(g_h2[n * 128 + c]);
    float wa = watt[c];
    float p1 = h1v * wa;
    float p2 = h2v * wa;
#pragma unroll
    for (int o = 16; o > 0; o >>= 1) {
        p1 += __shfl_down_sync(0xFFFFFFFFu, p1, o);
        p2 += __shfl_down_sync(0xFFFFFFFFu, p2, o);
    }
    __shared__ float s1[8], s2[8];
    __shared__ float a1s[2];
    int w = threadIdx.x >> 5;
    if ((threadIdx.x & 31) == 0) { s1[w] = p1; s2[w] = p2; }
    __syncthreads();
    if (c == 0) {
        int b = half * 4;
        float S1 = s1[b] + s1[b+1] + s1[b+2] + s1[b+3] + batt[0];
        float S2 = s2[b] + s2[b+1] + s2[b+2] + s2[b+3] + batt[0];
        a1s[half] = 1.0f / (1.0f + expf(S2 - S1));
    }
    __syncthreads();
    float a1 = a1s[half];
    float v = a1 * h1v + (1.0f - a1) * h2v;
    g_comb[n * 256 + 128 + c] = __float2half_rn(v);
}

// ================= launch =================
extern "C" void kernel_launch(void* const* d_in, const int* in_sizes, int n_in,
                              void* d_out, int out_size) {
    const float* x    = (const float*)d_in[0];
    const int*   ei32 = (const int*)d_in[1];
    const float* W_s1 = (const float*)d_in[2];
    const float* b_s1 = (const float*)d_in[3];
    const float* W_s2 = (const float*)d_in[4];
    const float* b_s2 = (const float*)d_in[5];
    const float* W_m1 = (const float*)d_in[6];
    const float* b_m1 = (const float*)d_in[7];
    const float* W_m21 = (const float*)d_in[8];
    const float* b_m21 = (const float*)d_in[9];
    const float* W_m22 = (const float*)d_in[10];
    const float* b_m22 = (const float*)d_in[11];
    const float* W_att = (const float*)d_in[12];
    const float* b_att = (const float*)d_in[13];
    const float* W_fc  = (const float*)d_in[14];
    const float* b_fc  = (const float*)d_in[15];
    float* out = (float*)d_out;

    __half *h1, *h2, *xh, *bufA, *aggx, *agg2, *comb, *wth, *wtl;
    cudaGetSymbolAddress((void**)&h1, g_h1);
    cudaGetSymbolAddress((void**)&h2, g_h2);
    cudaGetSymbolAddress((void**)&xh, g_xh);
    cudaGetSymbolAddress((void**)&bufA, g_bufA);
    cudaGetSymbolAddress((void**)&aggx, g_aggx);
    cudaGetSymbolAddress((void**)&agg2, g_agg2);
    cudaGetSymbolAddress((void**)&comb, g_comb);
    cudaGetSymbolAddress((void**)&wth, g_wth);
    cudaGetSymbolAddress((void**)&wtl, g_wtl);

    const int SM_L  = 128 * 128 * 2 + 2 * (128 * 128 * 2);  // 98304, occ 2, 512 thr
    const int SM_FC = 64 * 256 * 2 + 2 * (64 * 256 * 2);    // 98304, occ 2, 256 thr
    static bool attr_done = false;
    if (!attr_done) {
        cudaFuncSetAttribute(k_mma_shared<512, 128, 128, 128>, cudaFuncAttributeMaxDynamicSharedMemorySize, SM_L);
        cudaFuncSetAttribute(k_mma<512, 128, 128, 128>, cudaFuncAttributeMaxDynamicSharedMemorySize, SM_L);
        cudaFuncSetAttribute(k_mma<256, 64, 64, 256>,   cudaFuncAttributeMaxDynamicSharedMemorySize, SM_FC);
        attr_done = true;
    }

    const int TB = 256;
    const int initBlocks  = (N_NODES + TB - 1) / TB;
    const int countBlocks = (N_EDGES + TB - 1) / TB;
    const int convxBlocks = (N_NODES * 128 / 8) / TB;

    PrepB p;
    p.W[0] = W_s1;  p.K[0] = 128; p.N[0] = 128;
    p.W[1] = W_m21; p.K[1] = 128; p.N[1] = 128;
    p.W[2] = W_m1;  p.K[2] = 128; p.N[2] = 128;
    p.W[3] = W_s2;  p.K[3] = 128; p.N[3] = 128;
    p.W[4] = W_m22; p.K[4] = 128; p.N[4] = 128;
    p.W[5] = W_fc;  p.K[5] = 256; p.N[5] = 64;

    k_detect_init_prep<<<initBlocks + 6, TB>>>(ei32, p, initBlocks);
    k_count_convx<<<countBlocks + convxBlocks, TB>>>(ei32, x, xh, countBlocks);
    k_scan_dinv<<<1, 1024>>>();
    k_fill<<<countBlocks, TB>>>(ei32);

    k_agg128<<<N_NODES / 8, 256>>>(xh, aggx);

    const int MT128 = (N_NODES + 127) / 128;  // 391
    const int MT64  = (N_NODES + 63) / 64;    // 782

    // layer-1: one launch, shared A, 3 weight jobs per CTA
    {
        MJobs j = {};
        for (int q = 0; q < 3; q++) { j.A[q] = aggx; j.lda[q] = 128; }
        j.Bh[0] = wth + 0 * 16384; j.Bl[0] = wtl + 0 * 16384; j.bias[0] = b_s1;
        j.Ch[0] = bufA;       j.ldc[0] = 256;
        j.Bh[1] = wth + 1 * 16384; j.Bl[1] = wtl + 1 * 16384; j.bias[1] = b_m21;
        j.Ch[1] = bufA + 128; j.ldc[1] = 256;
        j.Bh[2] = wth + 2 * 16384; j.Bl[2] = wtl + 2 * 16384; j.bias[2] = b_m1;
        j.Ch[2] = h1; j.ldc[2] = 128;
        k_mma_shared<512, 128, 128, 128><<<dim3(1, MT128, 1), 512, SM_L>>>(j, 3, 1);
    }

    k_agg256<<<N_NODES / 8, 256>>>(bufA, agg2);

    // layer-2: per-job (different A slices)
    {
        MJobs j = {};
        j.A[0] = agg2;       j.lda[0] = 256;
        j.A[1] = agg2 + 128; j.lda[1] = 256;
        j.A[2] = j.A[0];     j.lda[2] = 256;
        j.Bh[0] = wth + 3 * 16384; j.Bl[0] = wtl + 3 * 16384; j.bias[0] = b_s2;
        j.Ch[0] = comb; j.ldc[0] = 256; j.split[0] = 1;
        j.Bh[1] = wth + 4 * 16384; j.Bl[1] = wtl + 4 * 16384; j.bias[1] = b_m22;
        j.Ch[1] = h2; j.ldc[1] = 128; j.split[1] = 1;
        j.Bh[2] = j.Bh[0]; j.Bl[2] = j.Bl[0]; j.bias[2] = j.bias[0];
        j.Ch[2] = j.Ch[0]; j.ldc[2] = j.ldc[0]; j.split[2] = 1;
        k_mma<512, 128, 128, 128><<<dim3(1, MT128, 2), 512, SM_L>>>(j, 1);
    }

    k_attn<<<N_NODES / 2, 256>>>(W_att, b_att);

    {
        MJobs j = {};
        for (int q = 0; q < 3; q++) {
            j.A[q] = comb; j.lda[q] = 256;
            j.Bh[q] = wth + 5 * 16384; j.Bl[q] = wtl + 5 * 16384;
            j.bias[q] = b_fc; j.C[q] = out; j.ldc[q] = 64; j.split[q] = 0;
        }
        k_mma<256, 64, 64, 256><<<dim3(1, MT64, 1), 256, SM_FC>>>(j, 0);
    }

    (void)in_sizes; (void)n_in; (void)out_size;
}

// round 16
// speedup vs baseline: 1.0287x; 1.0287x over previous
#include <cuda_runtime.h>
#include <cuda_fp16.h>
#include <math.h>
#include <cstdint>

#define N_NODES 50000
#define N_EDGES 800000

// ================= scratch =================
__device__ int   g_is64;
__device__ int   g_edeg[N_NODES];
__device__ float g_dinv[N_NODES];
__device__ int   g_rowptr[N_NODES + 1];
__device__ int   g_cursor[N_NODES];
__device__ int2  g_edge[N_EDGES];     // (src, wedge-bits) interleaved

// fp16 buffers
__device__ __half g_h1[N_NODES * 128];
__device__ __half g_h2[N_NODES * 128];
__device__ __half g_xh[N_NODES * 128];
__device__ __half g_bufA[N_NODES * 256];
__device__ __half g_aggx[N_NODES * 128];
__device__ __half g_agg2[N_NODES * 256];
__device__ __half g_comb[N_NODES * 256];
__device__ __half g_wth[6][16384];
__device__ __half g_wtl[6][16384];

// ================= helpers =================
__device__ __forceinline__ uint32_t smem_u32(const void* p) {
    uint32_t a;
    asm("{ .reg .u64 t; cvta.to.shared.u64 t, %1; cvt.u32.u64 %0, t; }" : "=r"(a) : "l"(p));
    return a;
}
__device__ __forceinline__ void ldsm_x4(uint32_t* r, uint32_t addr) {
    asm volatile("ldmatrix.sync.aligned.m8n8.x4.shared.b16 {%0,%1,%2,%3}, [%4];"
                 : "=r"(r[0]), "=r"(r[1]), "=r"(r[2]), "=r"(r[3]) : "r"(addr));
}
__device__ __forceinline__ void ldsm_x2(uint32_t* r, uint32_t addr) {
    asm volatile("ldmatrix.sync.aligned.m8n8.x2.shared.b16 {%0,%1}, [%2];"
                 : "=r"(r[0]), "=r"(r[1]) : "r"(addr));
}
__device__ __forceinline__ void mma_f16(float* d, const uint32_t* a, const uint32_t* b) {
    asm volatile("mma.sync.aligned.m16n8k16.row.col.f32.f16.f16.f32 "
                 "{%0,%1,%2,%3}, {%4,%5,%6,%7}, {%8,%9}, {%0,%1,%2,%3};"
                 : "+f"(d[0]), "+f"(d[1]), "+f"(d[2]), "+f"(d[3])
                 : "r"(a[0]), "r"(a[1]), "r"(a[2]), "r"(a[3]), "r"(b[0]), "r"(b[1]));
}
__device__ __forceinline__ void split_f16(float v, __half& h, __half& l) {
    __half hb = __float2half_rn(v);
    h = hb;
    l = __float2half_rn(v - __half2float(hb));
}

// ================= fused: detect + edeg zero + weight prep =================
struct PrepB { const float* W[6]; int K[6]; int N[6]; };
__global__ void k_detect_init_prep(const int* __restrict__ ei32, PrepB p, int nInitBlocks) {
    if ((int)blockIdx.x < nInitBlocks) {
        int i = blockIdx.x * blockDim.x + threadIdx.x;
        if (i < N_NODES) g_edeg[i] = 0;
        if (blockIdx.x == 0) {
            __shared__ int nz;
            if (threadIdx.x == 0) nz = 0;
            __syncthreads();
            int local = 0;
            for (int q = threadIdx.x; q < 2048; q += blockDim.x)
                if (ei32[2 * q + 1] != 0) local = 1;
            if (local) atomicOr(&nz, 1);
            __syncthreads();
            if (threadIdx.x == 0) g_is64 = nz ? 0 : 1;
        }
    } else {
        int b = blockIdx.x - nInitBlocks;   // 0..5
        const float* W = p.W[b];
        int K = p.K[b], N = p.N[b];
        for (int idx = threadIdx.x; idx < K * N; idx += blockDim.x) {
            int k = idx / N, n = idx % N;
            split_f16(W[idx], g_wth[b][n * K + k], g_wtl[b][n * K + k]);
        }
    }
}

// ================= fused: count + x->fp16 =================
__global__ void k_count_convx(const int* __restrict__ ei32, const float* __restrict__ x,
                              __half* __restrict__ xh, int nCountBlocks) {
    if ((int)blockIdx.x < nCountBlocks) {
        int e = blockIdx.x * blockDim.x + threadIdx.x;
        if (e < N_EDGES) {
            int d = g_is64 ? ei32[2 * (N_EDGES + e)] : ei32[N_EDGES + e];
            atomicAdd(&g_edeg[d], 1);
        }
    } else {
        int i = (blockIdx.x - nCountBlocks) * blockDim.x + threadIdx.x;
        const float4* xp = reinterpret_cast<const float4*>(x) + 2 * (size_t)i;
        float4 a = xp[0], b = xp[1];
        __half2 h[4];
        h[0] = {__float2half_rn(a.x), __float2half_rn(a.y)};
        h[1] = {__float2half_rn(a.z), __float2half_rn(a.w)};
        h[2] = {__float2half_rn(b.x), __float2half_rn(b.y)};
        h[3] = {__float2half_rn(b.z), __float2half_rn(b.w)};
        reinterpret_cast<uint4*>(xh)[i] = *reinterpret_cast<uint4*>(h);
    }
}

__global__ void k_scan_dinv() {
    __shared__ int part[1024];
    const int t = threadIdx.x;
    const int CH = (N_NODES + 1023) / 1024;
    int start = t * CH;
    int s = 0;
    for (int i = 0; i < CH; i++) { int idx = start + i; if (idx < N_NODES) s += g_edeg[idx]; }
    part[t] = s;
    __syncthreads();
    for (int off = 1; off < 1024; off <<= 1) {
        int v = (t >= off) ? part[t - off] : 0;
        __syncthreads();
        part[t] += v;
        __syncthreads();
    }
    int run = (t == 0) ? 0 : part[t - 1];
    for (int i = 0; i < CH; i++) {
        int idx = start + i;
        if (idx < N_NODES) {
            g_rowptr[idx] = run;
            g_cursor[idx] = run;
            g_dinv[idx] = rsqrtf((float)(g_edeg[idx] + 1));
            run += g_edeg[idx];
        }
    }
    if (t == 1023) g_rowptr[N_NODES] = run;
}

__global__ void k_fill(const int* __restrict__ ei32) {
    int e = blockIdx.x * blockDim.x + threadIdx.x;
    if (e < N_EDGES) {
        int s, d;
        if (g_is64) { s = ei32[2 * e]; d = ei32[2 * (N_EDGES + e)]; }
        else        { s = ei32[e];     d = ei32[N_EDGES + e]; }
        int p = atomicAdd(&g_cursor[d], 1);
        float w = g_dinv[s] * g_dinv[d];
        g_edge[p] = make_int2(s, __float_as_int(w));
    }
}

// ================= warp-per-node aggregation (fp16 gather, int2 edges) =================
__global__ __launch_bounds__(256, 8) void k_agg128(const __half* __restrict__ in,
                                                   __half* __restrict__ oh) {
    const int warp = threadIdx.x >> 5, lane = threadIdx.x & 31;
    const int n = blockIdx.x * 8 + warp;
    const int c4 = lane * 4;
    float dn = g_dinv[n];
    float acc0, acc1, acc2, acc3;
    {
        uint2 sv = *reinterpret_cast<const uint2*>(in + (size_t)n * 128 + c4);
        __half2 s0 = *reinterpret_cast<__half2*>(&sv.x);
        __half2 s1 = *reinterpret_cast<__half2*>(&sv.y);
        float w = dn * dn;
        acc0 = w * __half2float(s0.x); acc1 = w * __half2float(s0.y);
        acc2 = w * __half2float(s1.x); acc3 = w * __half2float(s1.y);
    }
    const int beg = g_rowptr[n], end = g_rowptr[n + 1];
    for (int base = beg; base < end; base += 32) {
        int cnt = end - base; if (cnt > 32) cnt = 32;
        int   col = 0; float wt = 0.0f;
        if (lane < cnt) {
            int2 ev = g_edge[base + lane];
            col = ev.x;
            wt = __int_as_float(ev.y);
        }
        for (int j = 0; j < cnt; j++) {
            int   idx = __shfl_sync(0xFFFFFFFFu, col, j);
            float ww  = __shfl_sync(0xFFFFFFFFu, wt,  j);
            uint2 gv = *reinterpret_cast<const uint2*>(in + (size_t)idx * 128 + c4);
            __half2 g0 = *reinterpret_cast<__half2*>(&gv.x);
            __half2 g1 = *reinterpret_cast<__half2*>(&gv.y);
            acc0 += ww * __half2float(g0.x); acc1 += ww * __half2float(g0.y);
            acc2 += ww * __half2float(g1.x); acc3 += ww * __half2float(g1.y);
        }
    }
    __half2 o0 = {__float2half_rn(acc0), __float2half_rn(acc1)};
    __half2 o1 = {__float2half_rn(acc2), __float2half_rn(acc3)};
    *reinterpret_cast<uint2*>(oh + (size_t)n * 128 + c4) = make_uint2(
        *reinterpret_cast<uint32_t*>(&o0), *reinterpret_cast<uint32_t*>(&o1));
}

__global__ __launch_bounds__(256, 8) void k_agg256(const __half* __restrict__ in,
                                                   __half* __restrict__ oh) {
    const int warp = threadIdx.x >> 5, lane = threadIdx.x & 31;
    const int n = blockIdx.x * 8 + warp;
    const int c8 = lane * 8;
    float dn = g_dinv[n];
    float acc[8];
    {
        uint4 sv = *reinterpret_cast<const uint4*>(in + (size_t)n * 256 + c8);
        const __half2* sh = reinterpret_cast<const __half2*>(&sv);
        float w = dn * dn;
#pragma unroll
        for (int q = 0; q < 4; q++) {
            acc[2 * q]     = w * __half2float(sh[q].x);
            acc[2 * q + 1] = w * __half2float(sh[q].y);
        }
    }
    const int beg = g_rowptr[n], end = g_rowptr[n + 1];
    for (int base = beg; base < end; base += 32) {
        int cnt = end - base; if (cnt > 32) cnt = 32;
        int   col = 0; float wt = 0.0f;
        if (lane < cnt) {
            int2 ev = g_edge[base + lane];
            col = ev.x;
            wt = __int_as_float(ev.y);
        }
        for (int j = 0; j < cnt; j++) {
            int   idx = __shfl_sync(0xFFFFFFFFu, col, j);
            float ww  = __shfl_sync(0xFFFFFFFFu, wt,  j);
            uint4 gv = *reinterpret_cast<const uint4*>(in + (size_t)idx * 256 + c8);
            const __half2* gh = reinterpret_cast<const __half2*>(&gv);
#pragma unroll
            for (int q = 0; q < 4; q++) {
                acc[2 * q]     += ww * __half2float(gh[q].x);
                acc[2 * q + 1] += ww * __half2float(gh[q].y);
            }
        }
    }
    __half2 hv[4];
#pragma unroll
    for (int q = 0; q < 4; q++)
        hv[q] = {__float2half_rn(acc[2 * q]), __float2half_rn(acc[2 * q + 1])};
    *reinterpret_cast<uint4*>(oh + (size_t)n * 256 + c8) = *reinterpret_cast<uint4*>(hv);
}

// ================= fp16 2-pass mma.sync GEMM (per-job grid.z form) =================
struct MJobs {
    const __half* A[3];
    const __half* Bh[3];
    const __half* Bl[3];
    const float*  bias[3];
    float*        C[3];
    __half*       Ch[3];
    int           lda[3];
    int           ldc[3];
    int           split[3];
};

template <int THREADS, int BM, int NN, int KK>
__global__ __launch_bounds__(THREADS, 2) void k_mma(MJobs jobs, int do_relu) {
    extern __shared__ __align__(16) unsigned char smem[];
    constexpr int NCH = KK / 8;
    constexpr int AB  = BM * KK * 2;
    constexpr int BB  = NN * KK * 2;
    constexpr int MWARPS = (THREADS == 512) ? 4 : 2;
    constexpr int MI  = BM / MWARPS / 16;
    constexpr int NI  = NN / 4 / 8;
    constexpr int KSTEPS = KK / 16;

    const int job = blockIdx.z;
    const int bm  = blockIdx.y * BM;
    const int tid = threadIdx.x;
    const int lane = tid & 31, warp = tid >> 5;
    const int wm = (warp >> 2) * (BM / MWARPS);
    const int wn = (warp & 3) * (NN / 4);

    {
        const __half* A = jobs.A[job];
        const int ldach = jobs.lda[job] / 8;
        uint4* s = reinterpret_cast<uint4*>(smem);
        for (int idx = tid; idx < BM * NCH; idx += THREADS) {
            int r = idx / NCH, cc = idx % NCH;
            long gr = bm + r; if (gr >= N_NODES) gr = N_NODES - 1;
            int sp = r * NCH + (cc ^ (r & 7));
            s[sp] = reinterpret_cast<const uint4*>(A)[gr * ldach + cc];
        }
        const uint4* bh = reinterpret_cast<const uint4*>(jobs.Bh[job]);
        const uint4* bl = reinterpret_cast<const uint4*>(jobs.Bl[job]);
        uint4* sb = reinterpret_cast<uint4*>(smem + AB);
        for (int idx = tid; idx < NN * NCH; idx += THREADS) {
            int r = idx / NCH, cc = idx % NCH;
            int sp = r * NCH + (cc ^ (r & 7));
            sb[sp]           = bh[idx];
            sb[sp + BB / 16] = bl[idx];
        }
    }
    __syncthreads();

    const uint32_t sbase = smem_u32(smem);
    const int group = lane >> 3, within = lane & 7;
    const int kaddA = group >> 1;
    uint32_t abyte[MI]; int rx[MI];
    {
        int mrow = wm + (group & 1) * 8 + within;
#pragma unroll
        for (int mi = 0; mi < MI; mi++) {
            int r = mrow + mi * 16;
            abyte[mi] = (uint32_t)(r * NCH) << 4;
            rx[mi] = r & 7;
        }
    }
    const int laneB = lane & 15;
    const int kaddB = laneB >> 3, withinB = laneB & 7;
    uint32_t bbyte[NI]; int nx[NI];
#pragma unroll
    for (int ni = 0; ni < NI; ni++) {
        int r = wn + ni * 8 + withinB;
        bbyte[ni] = (uint32_t)(r * NCH) << 4;
        nx[ni] = r & 7;
    }

    float acc[MI][NI][4];
#pragma unroll
    for (int mi = 0; mi < MI; mi++)
#pragma unroll
        for (int ni = 0; ni < NI; ni++)
#pragma unroll
            for (int q = 0; q < 4; q++) acc[mi][ni][q] = 0.0f;

#pragma unroll 1
    for (int pass = 0; pass < 2; pass++) {
        const uint32_t aoff = sbase;
        const uint32_t boff = sbase + AB + pass * BB;
#pragma unroll
        for (int s = 0; s < KSTEPS; s++) {
            const int kc = s * 2;
            uint32_t bf[NI][2];
#pragma unroll
            for (int ni = 0; ni < NI; ni++)
                ldsm_x2(bf[ni], boff + bbyte[ni] + ((uint32_t)((kc + kaddB) ^ nx[ni]) << 4));
#pragma unroll
            for (int mi = 0; mi < MI; mi++) {
                uint32_t af[4];
                ldsm_x4(af, aoff + abyte[mi] + ((uint32_t)((kc + kaddA) ^ rx[mi]) << 4));
#pragma unroll
                for (int ni = 0; ni < NI; ni++)
                    mma_f16(acc[mi][ni], af, bf[ni]);
            }
        }
    }

    const float* bias = jobs.bias[job];
    float* C = jobs.C[job];
    __half* Ch = jobs.Ch[job];
    const int ldc = jobs.ldc[job];
    const int splt = jobs.split[job];
    const int g = lane >> 2, tc = lane & 3;
#pragma unroll
    for (int mi = 0; mi < MI; mi++) {
#pragma unroll
        for (int ni = 0; ni < NI; ni++) {
            int n0 = wn + ni * 8 + tc * 2;
            float b0 = bias[n0], b1 = bias[n0 + 1];
            int m0 = bm + wm + mi * 16 + g;
            float v0 = acc[mi][ni][0] + b0, v1 = acc[mi][ni][1] + b1;
            float v2 = acc[mi][ni][2] + b0, v3 = acc[mi][ni][3] + b1;
            if (do_relu) {
                v0 = fmaxf(v0, 0.0f); v1 = fmaxf(v1, 0.0f);
                v2 = fmaxf(v2, 0.0f); v3 = fmaxf(v3, 0.0f);
            }
            if (splt) {
                if (m0 < N_NODES)
                    *reinterpret_cast<__half2*>(Ch + (size_t)m0 * ldc + n0) =
                        __half2{__float2half_rn(v0), __float2half_rn(v1)};
                if (m0 + 8 < N_NODES)
                    *reinterpret_cast<__half2*>(Ch + (size_t)(m0 + 8) * ldc + n0) =
                        __half2{__float2half_rn(v2), __float2half_rn(v3)};
            } else {
                if (m0 < N_NODES)
                    *reinterpret_cast<float2*>(C + (size_t)m0 * ldc + n0) = make_float2(v0, v1);
                if (m0 + 8 < N_NODES)
                    *reinterpret_cast<float2*>(C + (size_t)(m0 + 8) * ldc + n0) = make_float2(v2, v3);
            }
        }
    }
}

// ================= attention fusion (fp16 h1/h2) =================
__global__ void k_attn(const float* __restrict__ watt, const float* __restrict__ batt) {
    const int half = threadIdx.x >> 7;
    const int c = threadIdx.x & 127;
    const int n = blockIdx.x * 2 + half;
    float h1v = __half2float(g_h1[n * 128 + c]);
    float h2v = __half2float(g_h2[n * 128 + c]);
    float wa = watt[c];
    float p1 = h1v * wa;
    float p2 = h2v * wa;
#pragma unroll
    for (int o = 16; o > 0; o >>= 1) {
        p1 += __shfl_down_sync(0xFFFFFFFFu, p1, o);
        p2 += __shfl_down_sync(0xFFFFFFFFu, p2, o);
    }
    __shared__ float s1[8], s2[8];
    __shared__ float a1s[2];
    int w = threadIdx.x >> 5;
    if ((threadIdx.x & 31) == 0) { s1[w] = p1; s2[w] = p2; }
    __syncthreads();
    if (c == 0) {
        int b = half * 4;
        float S1 = s1[b] + s1[b+1] + s1[b+2] + s1[b+3] + batt[0];
        float S2 = s2[b] + s2[b+1] + s2[b+2] + s2[b+3] + batt[0];
        a1s[half] = 1.0f / (1.0f + expf(S2 - S1));
    }
    __syncthreads();
    float a1 = a1s[half];
    float v = a1 * h1v + (1.0f - a1) * h2v;
    g_comb[n * 256 + 128 + c] = __float2half_rn(v);
}

// ================= launch =================
extern "C" void kernel_launch(void* const* d_in, const int* in_sizes, int n_in,
                              void* d_out, int out_size) {
    const float* x    = (const float*)d_in[0];
    const int*   ei32 = (const int*)d_in[1];
    const float* W_s1 = (const float*)d_in[2];
    const float* b_s1 = (const float*)d_in[3];
    const float* W_s2 = (const float*)d_in[4];
    const float* b_s2 = (const float*)d_in[5];
    const float* W_m1 = (const float*)d_in[6];
    const float* b_m1 = (const float*)d_in[7];
    const float* W_m21 = (const float*)d_in[8];
    const float* b_m21 = (const float*)d_in[9];
    const float* W_m22 = (const float*)d_in[10];
    const float* b_m22 = (const float*)d_in[11];
    const float* W_att = (const float*)d_in[12];
    const float* b_att = (const float*)d_in[13];
    const float* W_fc  = (const float*)d_in[14];
    const float* b_fc  = (const float*)d_in[15];
    float* out = (float*)d_out;

    __half *h1, *h2, *xh, *bufA, *aggx, *agg2, *comb, *wth, *wtl;
    cudaGetSymbolAddress((void**)&h1, g_h1);
    cudaGetSymbolAddress((void**)&h2, g_h2);
    cudaGetSymbolAddress((void**)&xh, g_xh);
    cudaGetSymbolAddress((void**)&bufA, g_bufA);
    cudaGetSymbolAddress((void**)&aggx, g_aggx);
    cudaGetSymbolAddress((void**)&agg2, g_agg2);
    cudaGetSymbolAddress((void**)&comb, g_comb);
    cudaGetSymbolAddress((void**)&wth, g_wth);
    cudaGetSymbolAddress((void**)&wtl, g_wtl);

    const int SM_L  = 128 * 128 * 2 + 2 * (128 * 128 * 2);  // 98304, occ 2, 512 thr
    const int SM_FC = 64 * 256 * 2 + 2 * (64 * 256 * 2);    // 98304, occ 2, 256 thr
    static bool attr_done = false;
    if (!attr_done) {
        cudaFuncSetAttribute(k_mma<512, 128, 128, 128>, cudaFuncAttributeMaxDynamicSharedMemorySize, SM_L);
        cudaFuncSetAttribute(k_mma<256, 64, 64, 256>,   cudaFuncAttributeMaxDynamicSharedMemorySize, SM_FC);
        attr_done = true;
    }

    const int TB = 256;
    const int initBlocks  = (N_NODES + TB - 1) / TB;
    const int countBlocks = (N_EDGES + TB - 1) / TB;
    const int convxBlocks = (N_NODES * 128 / 8) / TB;

    PrepB p;
    p.W[0] = W_s1;  p.K[0] = 128; p.N[0] = 128;
    p.W[1] = W_m21; p.K[1] = 128; p.N[1] = 128;
    p.W[2] = W_m1;  p.K[2] = 128; p.N[2] = 128;
    p.W[3] = W_s2;  p.K[3] = 128; p.N[3] = 128;
    p.W[4] = W_m22; p.K[4] = 128; p.N[4] = 128;
    p.W[5] = W_fc;  p.K[5] = 256; p.N[5] = 64;

    k_detect_init_prep<<<initBlocks + 6, TB>>>(ei32, p, initBlocks);
    k_count_convx<<<countBlocks + convxBlocks, TB>>>(ei32, x, xh, countBlocks);
    k_scan_dinv<<<1, 1024>>>();
    k_fill<<<countBlocks, TB>>>(ei32);

    k_agg128<<<N_NODES / 8, 256>>>(xh, aggx);

    const int MT128 = (N_NODES + 127) / 128;  // 391
    const int MT64  = (N_NODES + 63) / 64;    // 782

    // layer-1: per-job grid.z=3 (R14 form)
    {
        MJobs j = {};
        for (int q = 0; q < 3; q++) { j.A[q] = aggx; j.lda[q] = 128; }
        j.Bh[0] = wth + 0 * 16384; j.Bl[0] = wtl + 0 * 16384; j.bias[0] = b_s1;
        j.Ch[0] = bufA;       j.ldc[0] = 256; j.split[0] = 1;
        j.Bh[1] = wth + 1 * 16384; j.Bl[1] = wtl + 1 * 16384; j.bias[1] = b_m21;
        j.Ch[1] = bufA + 128; j.ldc[1] = 256; j.split[1] = 1;
        j.Bh[2] = wth + 2 * 16384; j.Bl[2] = wtl + 2 * 16384; j.bias[2] = b_m1;
        j.Ch[2] = h1; j.ldc[2] = 128; j.split[2] = 1;
        k_mma<512, 128, 128, 128><<<dim3(1, MT128, 3), 512, SM_L>>>(j, 1);
    }

    k_agg256<<<N_NODES / 8, 256>>>(bufA, agg2);

    {
        MJobs j = {};
        j.A[0] = agg2;       j.lda[0] = 256;
        j.A[1] = agg2 + 128; j.lda[1] = 256;
        j.A[2] = j.A[0];     j.lda[2] = 256;
        j.Bh[0] = wth + 3 * 16384; j.Bl[0] = wtl + 3 * 16384; j.bias[0] = b_s2;
        j.Ch[0] = comb; j.ldc[0] = 256; j.split[0] = 1;
        j.Bh[1] = wth + 4 * 16384; j.Bl[1] = wtl + 4 * 16384; j.bias[1] = b_m22;
        j.Ch[1] = h2; j.ldc[1] = 128; j.split[1] = 1;
        j.Bh[2] = j.Bh[0]; j.Bl[2] = j.Bl[0]; j.bias[2] = j.bias[0];
        j.Ch[2] = j.Ch[0]; j.ldc[2] = j.ldc[0]; j.split[2] = 1;
        k_mma<512, 128, 128, 128><<<dim3(1, MT128, 2), 512, SM_L>>>(j, 1);
    }

    k_attn<<<N_NODES / 2, 256>>>(W_att, b_att);

    {
        MJobs j = {};
        for (int q = 0; q < 3; q++) {
            j.A[q] = comb; j.lda[q] = 256;
            j.Bh[q] = wth + 5 * 16384; j.Bl[q] = wtl + 5 * 16384;
            j.bias[q] = b_fc; j.C[q] = out; j.ldc[q] = 64; j.split[q] = 0;
        }
        k_mma<256, 64, 64, 256><<<dim3(1, MT64, 1), 256, SM_FC>>>(j, 0);
    }

    (void)in_sizes; (void)n_in; (void)out_size;
}

// round 17
// speedup vs baseline: 1.3844x; 1.3458x over previous
#include <cuda_runtime.h>
#include <cuda_fp16.h>
#include <math.h>
#include <cstdint>

#define N_NODES 50000
#define N_EDGES 800000
#define SCAN_BLOCKS 49   // ceil(50000/1024)

// ================= scratch =================
__device__ int   g_is64;
__device__ int   g_edeg[N_NODES];
__device__ float g_dinv[N_NODES];
__device__ int   g_rowptr[N_NODES + 1];
__device__ int   g_cursor[N_NODES];
__device__ int   g_bsum[SCAN_BLOCKS];
__device__ int2  g_edge[N_EDGES];     // (src, wedge-bits)

// fp16 buffers
__device__ __half g_h1[N_NODES * 128];
__device__ __half g_h2[N_NODES * 128];
__device__ __half g_xh[N_NODES * 128];
__device__ __half g_bufA[N_NODES * 256];
__device__ __half g_aggx[N_NODES * 128];
__device__ __half g_agg2[N_NODES * 256];
__device__ __half g_comb[N_NODES * 256];
__device__ __half g_wth[6][16384];
__device__ __half g_wtl[6][16384];

// ================= helpers =================
__device__ __forceinline__ uint32_t smem_u32(const void* p) {
    uint32_t a;
    asm("{ .reg .u64 t; cvta.to.shared.u64 t, %1; cvt.u32.u64 %0, t; }" : "=r"(a) : "l"(p));
    return a;
}
__device__ __forceinline__ void ldsm_x4(uint32_t* r, uint32_t addr) {
    asm volatile("ldmatrix.sync.aligned.m8n8.x4.shared.b16 {%0,%1,%2,%3}, [%4];"
                 : "=r"(r[0]), "=r"(r[1]), "=r"(r[2]), "=r"(r[3]) : "r"(addr));
}
__device__ __forceinline__ void ldsm_x2(uint32_t* r, uint32_t addr) {
    asm volatile("ldmatrix.sync.aligned.m8n8.x2.shared.b16 {%0,%1}, [%2];"
                 : "=r"(r[0]), "=r"(r[1]) : "r"(addr));
}
__device__ __forceinline__ void mma_f16(float* d, const uint32_t* a, const uint32_t* b) {
    asm volatile("mma.sync.aligned.m16n8k16.row.col.f32.f16.f16.f32 "
                 "{%0,%1,%2,%3}, {%4,%5,%6,%7}, {%8,%9}, {%0,%1,%2,%3};"
                 : "+f"(d[0]), "+f"(d[1]), "+f"(d[2]), "+f"(d[3])
                 : "r"(a[0]), "r"(a[1]), "r"(a[2]), "r"(a[3]), "r"(b[0]), "r"(b[1]));
}
__device__ __forceinline__ void split_f16(float v, __half& h, __half& l) {
    __half hb = __float2half_rn(v);
    h = hb;
    l = __float2half_rn(v - __half2float(hb));
}

// ================= fused: detect + edeg zero + weight prep =================
struct PrepB { const float* W[6]; int K[6]; int N[6]; };
__global__ void k_detect_init_prep(const int* __restrict__ ei32, PrepB p, int nInitBlocks) {
    if ((int)blockIdx.x < nInitBlocks) {
        int i = blockIdx.x * blockDim.x + threadIdx.x;
        if (i < N_NODES) g_edeg[i] = 0;
        if (blockIdx.x == 0) {
            __shared__ int nz;
            if (threadIdx.x == 0) nz = 0;
            __syncthreads();
            int local = 0;
            for (int q = threadIdx.x; q < 2048; q += blockDim.x)
                if (ei32[2 * q + 1] != 0) local = 1;
            if (local) atomicOr(&nz, 1);
            __syncthreads();
            if (threadIdx.x == 0) g_is64 = nz ? 0 : 1;
        }
    } else {
        int b = blockIdx.x - nInitBlocks;
        const float* W = p.W[b];
        int K = p.K[b], N = p.N[b];
        for (int idx = threadIdx.x; idx < K * N; idx += blockDim.x) {
            int k = idx / N, n = idx % N;
            split_f16(W[idx], g_wth[b][n * K + k], g_wtl[b][n * K + k]);
        }
    }
}

// ================= fused: count + x->fp16 =================
__global__ void k_count_convx(const int* __restrict__ ei32, const float* __restrict__ x,
                              __half* __restrict__ xh, int nCountBlocks) {
    if ((int)blockIdx.x < nCountBlocks) {
        int e = blockIdx.x * blockDim.x + threadIdx.x;
        if (e < N_EDGES) {
            int d = g_is64 ? ei32[2 * (N_EDGES + e)] : ei32[N_EDGES + e];
            atomicAdd(&g_edeg[d], 1);
        }
    } else {
        int i = (blockIdx.x - nCountBlocks) * blockDim.x + threadIdx.x;
        const float4* xp = reinterpret_cast<const float4*>(x) + 2 * (size_t)i;
        float4 a = xp[0], b = xp[1];
        __half2 h[4];
        h[0] = {__float2half_rn(a.x), __float2half_rn(a.y)};
        h[1] = {__float2half_rn(a.z), __float2half_rn(a.w)};
        h[2] = {__float2half_rn(b.x), __float2half_rn(b.y)};
        h[3] = {__float2half_rn(b.z), __float2half_rn(b.w)};
        reinterpret_cast<uint4*>(xh)[i] = *reinterpret_cast<uint4*>(h);
    }
}

// ================= 3-phase parallel scan =================
// Phase 1: per-block exclusive scan of g_edeg -> g_rowptr (block-local), totals -> g_bsum.
__global__ void k_scan1() {
    __shared__ int sh[1024];
    const int t = threadIdx.x;
    const int i = blockIdx.x * 1024 + t;
    int v = (i < N_NODES) ? g_edeg[i] : 0;
    sh[t] = v;
    __syncthreads();
    int acc = v;
    for (int off = 1; off < 1024; off <<= 1) {
        int u = (t >= off) ? sh[t - off] : 0;
        __syncthreads();
        acc += u;
        sh[t] = acc;
        __syncthreads();
    }
    // sh[t] = inclusive prefix; exclusive = inclusive - v
    if (i < N_NODES) g_rowptr[i] = acc - v;
    if (t == 1023) g_bsum[blockIdx.x] = acc;
}

// Phase 2: exclusive scan of 49 block sums (single warp); set rowptr[N].
__global__ void k_scan2() {
    if (threadIdx.x == 0) {
        int run = 0;
        for (int b = 0; b < SCAN_BLOCKS; b++) {
            int v = g_bsum[b];
            g_bsum[b] = run;
            run += v;
        }
        g_rowptr[N_NODES] = run;
    }
}

// Phase 3: add offsets, emit rowptr/cursor/dinv.
__global__ void k_scan3() {
    const int i = blockIdx.x * 1024 + threadIdx.x;
    if (i < N_NODES) {
        int r = g_rowptr[i] + g_bsum[blockIdx.x];
        g_rowptr[i] = r;
        g_cursor[i] = r;
        g_dinv[i] = rsqrtf((float)(g_edeg[i] + 1));
    }
}

__global__ void k_fill(const int* __restrict__ ei32) {
    int e = blockIdx.x * blockDim.x + threadIdx.x;
    if (e < N_EDGES) {
        int s, d;
        if (g_is64) { s = ei32[2 * e]; d = ei32[2 * (N_EDGES + e)]; }
        else        { s = ei32[e];     d = ei32[N_EDGES + e]; }
        int p = atomicAdd(&g_cursor[d], 1);
        float w = g_dinv[s] * g_dinv[d];
        g_edge[p] = make_int2(s, __float_as_int(w));
    }
}

// ================= warp-per-node aggregation (fp16 gather, int2 edges) =================
__global__ __launch_bounds__(256, 8) void k_agg128(const __half* __restrict__ in,
                                                   __half* __restrict__ oh) {
    const int warp = threadIdx.x >> 5, lane = threadIdx.x & 31;
    const int n = blockIdx.x * 8 + warp;
    const int c4 = lane * 4;
    float dn = g_dinv[n];
    float acc0, acc1, acc2, acc3;
    {
        uint2 sv = *reinterpret_cast<const uint2*>(in + (size_t)n * 128 + c4);
        __half2 s0 = *reinterpret_cast<__half2*>(&sv.x);
        __half2 s1 = *reinterpret_cast<__half2*>(&sv.y);
        float w = dn * dn;
        acc0 = w * __half2float(s0.x); acc1 = w * __half2float(s0.y);
        acc2 = w * __half2float(s1.x); acc3 = w * __half2float(s1.y);
    }
    const int beg = g_rowptr[n], end = g_rowptr[n + 1];
    for (int base = beg; base < end; base += 32) {
        int cnt = end - base; if (cnt > 32) cnt = 32;
        int   col = 0; float wt = 0.0f;
        if (lane < cnt) {
            int2 ev = g_edge[base + lane];
            col = ev.x;
            wt = __int_as_float(ev.y);
        }
        for (int j = 0; j < cnt; j++) {
            int   idx = __shfl_sync(0xFFFFFFFFu, col, j);
            float ww  = __shfl_sync(0xFFFFFFFFu, wt,  j);
            uint2 gv = *reinterpret_cast<const uint2*>(in + (size_t)idx * 128 + c4);
            __half2 g0 = *reinterpret_cast<__half2*>(&gv.x);
            __half2 g1 = *reinterpret_cast<__half2*>(&gv.y);
            acc0 += ww * __half2float(g0.x); acc1 += ww * __half2float(g0.y);
            acc2 += ww * __half2float(g1.x); acc3 += ww * __half2float(g1.y);
        }
    }
    __half2 o0 = {__float2half_rn(acc0), __float2half_rn(acc1)};
    __half2 o1 = {__float2half_rn(acc2), __float2half_rn(acc3)};
    *reinterpret_cast<uint2*>(oh + (size_t)n * 128 + c4) = make_uint2(
        *reinterpret_cast<uint32_t*>(&o0), *reinterpret_cast<uint32_t*>(&o1));
}

__global__ __launch_bounds__(256, 8) void k_agg256(const __half* __restrict__ in,
                                                   __half* __restrict__ oh) {
    const int warp = threadIdx.x >> 5, lane = threadIdx.x & 31;
    const int n = blockIdx.x * 8 + warp;
    const int c8 = lane * 8;
    float dn = g_dinv[n];
    float acc[8];
    {
        uint4 sv = *reinterpret_cast<const uint4*>(in + (size_t)n * 256 + c8);
        const __half2* sh = reinterpret_cast<const __half2*>(&sv);
        float w = dn * dn;
#pragma unroll
        for (int q = 0; q < 4; q++) {
            acc[2 * q]     = w * __half2float(sh[q].x);
            acc[2 * q + 1] = w * __half2float(sh[q].y);
        }
    }
    const int beg = g_rowptr[n], end = g_rowptr[n + 1];
    for (int base = beg; base < end; base += 32) {
        int cnt = end - base; if (cnt > 32) cnt = 32;
        int   col = 0; float wt = 0.0f;
        if (lane < cnt) {
            int2 ev = g_edge[base + lane];
            col = ev.x;
            wt = __int_as_float(ev.y);
        }
        for (int j = 0; j < cnt; j++) {
            int   idx = __shfl_sync(0xFFFFFFFFu, col, j);
            float ww  = __shfl_sync(0xFFFFFFFFu, wt,  j);
            uint4 gv = *reinterpret_cast<const uint4*>(in + (size_t)idx * 256 + c8);
            const __half2* gh = reinterpret_cast<const __half2*>(&gv);
#pragma unroll
            for (int q = 0; q < 4; q++) {
                acc[2 * q]     += ww * __half2float(gh[q].x);
                acc[2 * q + 1] += ww * __half2float(gh[q].y);
            }
        }
    }
    __half2 hv[4];
#pragma unroll
    for (int q = 0; q < 4; q++)
        hv[q] = {__float2half_rn(acc[2 * q]), __float2half_rn(acc[2 * q + 1])};
    *reinterpret_cast<uint4*>(oh + (size_t)n * 256 + c8) = *reinterpret_cast<uint4*>(hv);
}

// ================= fp16 2-pass mma.sync GEMM (per-job grid.z form) =================
struct MJobs {
    const __half* A[3];
    const __half* Bh[3];
    const __half* Bl[3];
    const float*  bias[3];
    float*        C[3];
    __half*       Ch[3];
    int           lda[3];
    int           ldc[3];
    int           split[3];
};

template <int THREADS, int BM, int NN, int KK>
__global__ __launch_bounds__(THREADS, 2) void k_mma(MJobs jobs, int do_relu) {
    extern __shared__ __align__(16) unsigned char smem[];
    constexpr int NCH = KK / 8;
    constexpr int AB  = BM * KK * 2;
    constexpr int BB  = NN * KK * 2;
    constexpr int MWARPS = (THREADS == 512) ? 4 : 2;
    constexpr int MI  = BM / MWARPS / 16;
    constexpr int NI  = NN / 4 / 8;
    constexpr int KSTEPS = KK / 16;

    const int job = blockIdx.z;
    const int bm  = blockIdx.y * BM;
    const int tid = threadIdx.x;
    const int lane = tid & 31, warp = tid >> 5;
    const int wm = (warp >> 2) * (BM / MWARPS);
    const int wn = (warp & 3) * (NN / 4);

    {
        const __half* A = jobs.A[job];
        const int ldach = jobs.lda[job] / 8;
        uint4* s = reinterpret_cast<uint4*>(smem);
        for (int idx = tid; idx < BM * NCH; idx += THREADS) {
            int r = idx / NCH, cc = idx % NCH;
            long gr = bm + r; if (gr >= N_NODES) gr = N_NODES - 1;
            int sp = r * NCH + (cc ^ (r & 7));
            s[sp] = reinterpret_cast<const uint4*>(A)[gr * ldach + cc];
        }
        const uint4* bh = reinterpret_cast<const uint4*>(jobs.Bh[job]);
        const uint4* bl = reinterpret_cast<const uint4*>(jobs.Bl[job]);
        uint4* sb = reinterpret_cast<uint4*>(smem + AB);
        for (int idx = tid; idx < NN * NCH; idx += THREADS) {
            int r = idx / NCH, cc = idx % NCH;
            int sp = r * NCH + (cc ^ (r & 7));
            sb[sp]           = bh[idx];
            sb[sp + BB / 16] = bl[idx];
        }
    }
    __syncthreads();

    const uint32_t sbase = smem_u32(smem);
    const int group = lane >> 3, within = lane & 7;
    const int kaddA = group >> 1;
    uint32_t abyte[MI]; int rx[MI];
    {
        int mrow = wm + (group & 1) * 8 + within;
#pragma unroll
        for (int mi = 0; mi < MI; mi++) {
            int r = mrow + mi * 16;
            abyte[mi] = (uint32_t)(r * NCH) << 4;
            rx[mi] = r & 7;
        }
    }
    const int laneB = lane & 15;
    const int kaddB = laneB >> 3, withinB = laneB & 7;
    uint32_t bbyte[NI]; int nx[NI];
#pragma unroll
    for (int ni = 0; ni < NI; ni++) {
        int r = wn + ni * 8 + withinB;
        bbyte[ni] = (uint32_t)(r * NCH) << 4;
        nx[ni] = r & 7;
    }

    float acc[MI][NI][4];
#pragma unroll
    for (int mi = 0; mi < MI; mi++)
#pragma unroll
        for (int ni = 0; ni < NI; ni++)
#pragma unroll
            for (int q = 0; q < 4; q++) acc[mi][ni][q] = 0.0f;

#pragma unroll 1
    for (int pass = 0; pass < 2; pass++) {
        const uint32_t aoff = sbase;
        const uint32_t boff = sbase + AB + pass * BB;
#pragma unroll
        for (int s = 0; s < KSTEPS; s++) {
            const int kc = s * 2;
            uint32_t bf[NI][2];
#pragma unroll
            for (int ni = 0; ni < NI; ni++)
                ldsm_x2(bf[ni], boff + bbyte[ni] + ((uint32_t)((kc + kaddB) ^ nx[ni]) << 4));
#pragma unroll
            for (int mi = 0; mi < MI; mi++) {
                uint32_t af[4];
                ldsm_x4(af, aoff + abyte[mi] + ((uint32_t)((kc + kaddA) ^ rx[mi]) << 4));
#pragma unroll
                for (int ni = 0; ni < NI; ni++)
                    mma_f16(acc[mi][ni], af, bf[ni]);
            }
        }
    }

    const float* bias = jobs.bias[job];
    float* C = jobs.C[job];
    __half* Ch = jobs.Ch[job];
    const int ldc = jobs.ldc[job];
    const int splt = jobs.split[job];
    const int g = lane >> 2, tc = lane & 3;
#pragma unroll
    for (int mi = 0; mi < MI; mi++) {
#pragma unroll
        for (int ni = 0; ni < NI; ni++) {
            int n0 = wn + ni * 8 + tc * 2;
            float b0 = bias[n0], b1 = bias[n0 + 1];
            int m0 = bm + wm + mi * 16 + g;
            float v0 = acc[mi][ni][0] + b0, v1 = acc[mi][ni][1] + b1;
            float v2 = acc[mi][ni][2] + b0, v3 = acc[mi][ni][3] + b1;
            if (do_relu) {
                v0 = fmaxf(v0, 0.0f); v1 = fmaxf(v1, 0.0f);
                v2 = fmaxf(v2, 0.0f); v3 = fmaxf(v3, 0.0f);
            }
            if (splt) {
                if (m0 < N_NODES)
                    *reinterpret_cast<__half2*>(Ch + (size_t)m0 * ldc + n0) =
                        __half2{__float2half_rn(v0), __float2half_rn(v1)};
                if (m0 + 8 < N_NODES)
                    *reinterpret_cast<__half2*>(Ch + (size_t)(m0 + 8) * ldc + n0) =
                        __half2{__float2half_rn(v2), __float2half_rn(v3)};
            } else {
                if (m0 < N_NODES)
                    *reinterpret_cast<float2*>(C + (size_t)m0 * ldc + n0) = make_float2(v0, v1);
                if (m0 + 8 < N_NODES)
                    *reinterpret_cast<float2*>(C + (size_t)(m0 + 8) * ldc + n0) = make_float2(v2, v3);
            }
        }
    }
}

// ================= attention fusion (fp16 h1/h2) =================
__global__ void k_attn(const float* __restrict__ watt, const float* __restrict__ batt) {
    const int half = threadIdx.x >> 7;
    const int c = threadIdx.x & 127;
    const int n = blockIdx.x * 2 + half;
    float h1v = __half2float(g_h1[n * 128 + c]);
    float h2v = __half2float(g_h2[n * 128 + c]);
    float wa = watt[c];
    float p1 = h1v * wa;
    float p2 = h2v * wa;
#pragma unroll
    for (int o = 16; o > 0; o >>= 1) {
        p1 += __shfl_down_sync(0xFFFFFFFFu, p1, o);
        p2 += __shfl_down_sync(0xFFFFFFFFu, p2, o);
    }
    __shared__ float s1[8], s2[8];
    __shared__ float a1s[2];
    int w = threadIdx.x >> 5;
    if ((threadIdx.x & 31) == 0) { s1[w] = p1; s2[w] = p2; }
    __syncthreads();
    if (c == 0) {
        int b = half * 4;
        float S1 = s1[b] + s1[b+1] + s1[b+2] + s1[b+3] + batt[0];
        float S2 = s2[b] + s2[b+1] + s2[b+2] + s2[b+3] + batt[0];
        a1s[half] = 1.0f / (1.0f + expf(S2 - S1));
    }
    __syncthreads();
    float a1 = a1s[half];
    float v = a1 * h1v + (1.0f - a1) * h2v;
    g_comb[n * 256 + 128 + c] = __float2half_rn(v);
}

// ================= launch =================
extern "C" void kernel_launch(void* const* d_in, const int* in_sizes, int n_in,
                              void* d_out, int out_size) {
    const float* x    = (const float*)d_in[0];
    const int*   ei32 = (const int*)d_in[1];
    const float* W_s1 = (const float*)d_in[2];
    const float* b_s1 = (const float*)d_in[3];
    const float* W_s2 = (const float*)d_in[4];
    const float* b_s2 = (const float*)d_in[5];
    const float* W_m1 = (const float*)d_in[6];
    const float* b_m1 = (const float*)d_in[7];
    const float* W_m21 = (const float*)d_in[8];
    const float* b_m21 = (const float*)d_in[9];
    const float* W_m22 = (const float*)d_in[10];
    const float* b_m22 = (const float*)d_in[11];
    const float* W_att = (const float*)d_in[12];
    const float* b_att = (const float*)d_in[13];
    const float* W_fc  = (const float*)d_in[14];
    const float* b_fc  = (const float*)d_in[15];
    float* out = (float*)d_out;

    __half *h1, *h2, *xh, *bufA, *aggx, *agg2, *comb, *wth, *wtl;
    cudaGetSymbolAddress((void**)&h1, g_h1);
    cudaGetSymbolAddress((void**)&h2, g_h2);
    cudaGetSymbolAddress((void**)&xh, g_xh);
    cudaGetSymbolAddress((void**)&bufA, g_bufA);
    cudaGetSymbolAddress((void**)&aggx, g_aggx);
    cudaGetSymbolAddress((void**)&agg2, g_agg2);
    cudaGetSymbolAddress((void**)&comb, g_comb);
    cudaGetSymbolAddress((void**)&wth, g_wth);
    cudaGetSymbolAddress((void**)&wtl, g_wtl);

    const int SM_L  = 128 * 128 * 2 + 2 * (128 * 128 * 2);  // 98304, occ 2, 512 thr
    const int SM_FC = 64 * 256 * 2 + 2 * (64 * 256 * 2);    // 98304, occ 2, 256 thr
    static bool attr_done = false;
    if (!attr_done) {
        cudaFuncSetAttribute(k_mma<512, 128, 128, 128>, cudaFuncAttributeMaxDynamicSharedMemorySize, SM_L);
        cudaFuncSetAttribute(k_mma<256, 64, 64, 256>,   cudaFuncAttributeMaxDynamicSharedMemorySize, SM_FC);
        attr_done = true;
    }

    const int TB = 256;
    const int initBlocks  = (N_NODES + TB - 1) / TB;
    const int countBlocks = (N_EDGES + TB - 1) / TB;
    const int convxBlocks = (N_NODES * 128 / 8) / TB;

    PrepB p;
    p.W[0] = W_s1;  p.K[0] = 128; p.N[0] = 128;
    p.W[1] = W_m21; p.K[1] = 128; p.N[1] = 128;
    p.W[2] = W_m1;  p.K[2] = 128; p.N[2] = 128;
    p.W[3] = W_s2;  p.K[3] = 128; p.N[3] = 128;
    p.W[4] = W_m22; p.K[4] = 128; p.N[4] = 128;
    p.W[5] = W_fc;  p.K[5] = 256; p.N[5] = 64;

    k_detect_init_prep<<<initBlocks + 6, TB>>>(ei32, p, initBlocks);
    k_count_convx<<<countBlocks + convxBlocks, TB>>>(ei32, x, xh, countBlocks);
    k_scan1<<<SCAN_BLOCKS, 1024>>>();
    k_scan2<<<1, 32>>>();
    k_scan3<<<SCAN_BLOCKS, 1024>>>();
    k_fill<<<countBlocks, TB>>>(ei32);

    k_agg128<<<N_NODES / 8, 256>>>(xh, aggx);

    const int MT128 = (N_NODES + 127) / 128;  // 391
    const int MT64  = (N_NODES + 63) / 64;    // 782

    // layer-1: per-job grid.z=3
    {
        MJobs j = {};
        for (int q = 0; q < 3; q++) { j.A[q] = aggx; j.lda[q] = 128; }
        j.Bh[0] = wth + 0 * 16384; j.Bl[0] = wtl + 0 * 16384; j.bias[0] = b_s1;
        j.Ch[0] = bufA;       j.ldc[0] = 256; j.split[0] = 1;
        j.Bh[1] = wth + 1 * 16384; j.Bl[1] = wtl + 1 * 16384; j.bias[1] = b_m21;
        j.Ch[1] = bufA + 128; j.ldc[1] = 256; j.split[1] = 1;
        j.Bh[2] = wth + 2 * 16384; j.Bl[2] = wtl + 2 * 16384; j.bias[2] = b_m1;
        j.Ch[2] = h1; j.ldc[2] = 128; j.split[2] = 1;
        k_mma<512, 128, 128, 128><<<dim3(1, MT128, 3), 512, SM_L>>>(j, 1);
    }

    k_agg256<<<N_NODES / 8, 256>>>(bufA, agg2);

    {
        MJobs j = {};
        j.A[0] = agg2;       j.lda[0] = 256;
        j.A[1] = agg2 + 128; j.lda[1] = 256;
        j.A[2] = j.A[0];     j.lda[2] = 256;
        j.Bh[0] = wth + 3 * 16384; j.Bl[0] = wtl + 3 * 16384; j.bias[0] = b_s2;
        j.Ch[0] = comb; j.ldc[0] = 256; j.split[0] = 1;
        j.Bh[1] = wth + 4 * 16384; j.Bl[1] = wtl + 4 * 16384; j.bias[1] = b_m22;
        j.Ch[1] = h2; j.ldc[1] = 128; j.split[1] = 1;
        j.Bh[2] = j.Bh[0]; j.Bl[2] = j.Bl[0]; j.bias[2] = j.bias[0];
        j.Ch[2] = j.Ch[0]; j.ldc[2] = j.ldc[0]; j.split[2] = 1;
        k_mma<512, 128, 128, 128><<<dim3(1, MT128, 2), 512, SM_L>>>(j, 1);
    }

    k_attn<<<N_NODES / 2, 256>>>(W_att, b_att);

    {
        MJobs j = {};
        for (int q = 0; q < 3; q++) {
            j.A[q] = comb; j.lda[q] = 256;
            j.Bh[q] = wth + 5 * 16384; j.Bl[q] = wtl + 5 * 16384;
            j.bias[q] = b_fc; j.C[q] = out; j.ldc[q] = 64; j.split[q] = 0;
        }
        k_mma<256, 64, 64, 256><<<dim3(1, MT64, 1), 256, SM_FC>>>(j, 0);
    }

    (void)in_sizes; (void)n_in; (void)out_size;
}